// round 7
// baseline (speedup 1.0000x reference)
#include <cuda_runtime.h>
#include <stdint.h>

// Viterbi HMM decode: B=512, T=4096, S=16.  Output = float32 path.
//
// R7 vs R6 (391us): lazy half-merge removes one serial SHFL per step.
//  Each half h keeps only its partial max vh[j] (over predecessors
//  i in [8h,8h+8)) and its partial argmax. The true delta[i] =
//  fmax(v0[i],v1[i]) + e is materialized by NEXT step's consumers:
//  two parallel width-32 shuffles per predecessor fetch both partials,
//  fmax (exact) + add e + add A reproduce R6's c[i] bit-for-bit.
//  The psi argmax merge (shfl_xor 16 + cmp) is off the delta chain.
//
// K2/K3 backtrack machinery unchanged from R6.

#define T_LEN  4096
#define NSTEPS 4095
#define TILE   256
#define NTILE  16
#define B_TOT  512
#define FULL   0xFFFFFFFFu

__device__ unsigned char g_psi [B_TOT][T_LEN][16];          // 32 MB
__device__ unsigned char g_cand[B_TOT][NTILE][TILE][16];    // 32 MB
__device__ unsigned char g_map [B_TOT][NTILE][16];          // 128 KB
__device__ int           g_zT  [B_TOT];

// ---------------- K1: forward pass ----------------
__global__ void __launch_bounds__(128)
hmm_forward_kernel(const float* __restrict__ inputs,
                   const float* __restrict__ hmm)
{
    const int warp = threadIdx.x >> 5;
    const int lane = threadIdx.x & 31;
    const int j    = lane & 15;               // state (halves mirror)
    const int i0   = (lane & 16) >> 1;        // 0 or 8: this half's pred base
    const int b    = blockIdx.x * 4 + warp;
    const float* xrow  = inputs + b * T_LEN;
    const float* trans = hmm;                 // unit 0 only

    // ---- log_A rows for this half; log_pi[j] ----
    float s = 0.0f;
    #pragma unroll
    for (int k = 0; k < 16; k++) s = __fadd_rn(s, trans[j * 16 + k]);
    float ls = logf(s);                       // lane j: log(rowsum[j])
    float Ah[8];
    #pragma unroll
    for (int q = 0; q < 8; q++) {
        int i = i0 + q;
        float lt  = logf(trans[i * 16 + j]);
        float lsi = __shfl_sync(FULL, ls, i, 16);
        Ah[q] = __fsub_rn(lt, lsi);
    }
    float log_pi = __fsub_rn(logf(trans[j]), __shfl_sync(FULL, ls, 0, 16));

    const float C_NH = -0.9189385332046727f;  // -0.5*log(2*pi) fp32

    // invariant: vh = this half's partial max (pre-emission); e_pend = pending
    // emission add. delta[j] == fmax(v0[j],v1[j]) + e_pend (exact fmax).
    // init: both halves' partial = log_pi[j]; e_pend = emit(x0).
    float x0 = xrow[0];
    float vh = log_pi;
    float e_pend = __fadd_rn(__fmul_rn(__fmul_rn(-0.5f, x0), x0), C_NH);

    unsigned char* psi_b = &g_psi[b][0][0];
    const bool store_lane = (lane < 16);
    const bool half0 = (i0 == 0);

    auto do_step = [&](float x, int kidx) {
        // gather both halves' partials for my 8 predecessors (width-32 shfl)
        float c[8];
        #pragma unroll
        for (int q = 0; q < 8; q++) {
            float s0 = __shfl_sync(FULL, vh, i0 + q);        // v[i][0]
            float s1 = __shfl_sync(FULL, vh, i0 + q + 16);   // v[i][1]
            float dm = fmaxf(s0, s1);                        // exact merge
            c[q] = __fadd_rn(__fadd_rn(dm, e_pend), Ah[q]);  // == delta[i]+A
        }
        // emission for THIS step (consumed next step) — off the chain
        float e_new = __fadd_rn(__fmul_rn(__fmul_rn(-0.5f, x), x), C_NH);

        // 8-way max (pure FMNMX chain) + first-occurrence argmax (trailing)
        float v4[4]; int id4[4];
        #pragma unroll
        for (int q = 0; q < 4; q++) {
            bool p = c[2*q] >= c[2*q+1];
            v4[q]  = fmaxf(c[2*q], c[2*q+1]);
            id4[q] = p ? (2*q) : (2*q + 1);
        }
        float v2[2]; int id2[2];
        #pragma unroll
        for (int q = 0; q < 2; q++) {
            bool p = v4[2*q] >= v4[2*q+1];
            v2[q]  = fmaxf(v4[2*q], v4[2*q+1]);
            id2[q] = p ? id4[2*q] : id4[2*q+1];
        }
        bool pl = v2[0] >= v2[1];
        float vn = fmaxf(v2[0], v2[1]);
        int argh = i0 + (pl ? id2[0] : id2[1]);

        // psi merge across halves — feeds only the byte store, not delta
        float vo = __shfl_xor_sync(FULL, vn, 16);
        int   ao = __shfl_xor_sync(FULL, argh, 16);
        bool takeMine = half0 ? (vn >= vo) : (vn > vo);
        int arg = takeMine ? argh : ao;
        if (store_lane) psi_b[kidx * 16 + j] = (unsigned char)arg;

        vh = vn;
        e_pend = e_new;
    };

    // forward: 511 blocks of 8 steps + 7 tail, input prefetched 8 ahead
    float xs[8];
    #pragma unroll
    for (int k = 0; k < 8; k++) xs[k] = __ldg(xrow + 1 + k);
    int t = 1;
    for (int blk = 0; blk < 511; blk++) {
        float xn[8];
        #pragma unroll
        for (int k = 0; k < 8; k++) {
            int nt = t + 8 + k;
            nt = nt < T_LEN ? nt : T_LEN - 1;
            xn[k] = __ldg(xrow + nt);
        }
        #pragma unroll
        for (int k = 0; k < 8; k++) do_step(xs[k], t - 1 + k);
        #pragma unroll
        for (int k = 0; k < 8; k++) xs[k] = xn[k];
        t += 8;
    }
    #pragma unroll
    for (int k = 0; k < 7; k++) do_step(xs[k], t - 1 + k);   // t = 4089..4095

    __syncwarp();

    // materialize final delta, then zT = argmax (first occurrence)
    float vo = __shfl_xor_sync(FULL, vh, 16);
    float delta = __fadd_rn(fmaxf(vh, vo), e_pend);
    float v = delta; int zi = j;
    #pragma unroll
    for (int o = 8; o > 0; o >>= 1) {
        float v2 = __shfl_xor_sync(FULL, v, o, 16);
        int   i2 = __shfl_xor_sync(FULL, zi, o, 16);
        if (v2 > v || (v2 == v && i2 < zi)) { v = v2; zi = i2; }
    }
    if (lane == 0) g_zT[b] = zi;
}

// ---------------- K2: per-tile candidate chase ----------------
__global__ void __launch_bounds__(128)
hmm_chase_kernel()
{
    __shared__ unsigned char s_psi[4][TILE * 16];   // 16 KB

    const int warp = threadIdx.x >> 5;
    const int lane = threadIdx.x & 31;
    const int b    = blockIdx.x;
    const int tile = blockIdx.y * 4 + warp;

    const uint4* src = reinterpret_cast<const uint4*>(&g_psi[b][tile * TILE][0]);
    uint4* dst = reinterpret_cast<uint4*>(s_psi[warp]);
    #pragma unroll
    for (int i = 0; i < 8; i++) dst[lane + 32 * i] = src[lane + 32 * i];
    __syncwarp();

    int z = lane & 15;
    const int kmax = (tile == NTILE - 1) ? (TILE - 2) : (TILE - 1);
    const bool st = (lane < 16);
    unsigned char* cand = &g_cand[b][tile][0][0];
    for (int k = kmax; k >= 0; k--) {
        z = s_psi[warp][k * 16 + z];
        if (st) cand[k * 16 + lane] = (unsigned char)z;
    }
    if (st) g_map[b][tile][lane] = (unsigned char)z;
}

// ---------------- K3: compose maps + emit path ----------------
__global__ void __launch_bounds__(128)
hmm_emit_kernel(float* __restrict__ out)
{
    __shared__ unsigned char e_tile[NTILE];
    const int b = blockIdx.x;

    if (threadIdx.x == 0) {
        int z = g_zT[b];
        e_tile[NTILE - 1] = (unsigned char)z;
        #pragma unroll
        for (int tau = NTILE - 1; tau >= 1; tau--) {
            z = g_map[b][tau][z];
            e_tile[tau - 1] = (unsigned char)z;
        }
    }
    __syncthreads();

    float* orow = out + b * T_LEN;
    for (int t = threadIdx.x; t < NSTEPS; t += 128) {
        int tau = t >> 8, k = t & (TILE - 1);
        orow[t] = (float)g_cand[b][tau][k][e_tile[tau]];
    }
    if (threadIdx.x == 0) orow[T_LEN - 1] = (float)g_zT[b];
}

extern "C" void kernel_launch(void* const* d_in, const int* in_sizes, int n_in,
                              void* d_out, int out_size)
{
    const float* inputs;
    const float* hmm;
    if (in_sizes[0] < in_sizes[1]) {
        hmm    = (const float*)d_in[0];
        inputs = (const float*)d_in[1];
    } else {
        inputs = (const float*)d_in[0];
        hmm    = (const float*)d_in[1];
    }
    hmm_forward_kernel<<<128, 128>>>(inputs, hmm);
    hmm_chase_kernel<<<dim3(B_TOT, 4), 128>>>();
    hmm_emit_kernel<<<B_TOT, 128>>>((float*)d_out);
}

// round 8
// speedup vs baseline: 1.5902x; 1.5902x over previous
#include <cuda_runtime.h>
#include <stdint.h>

// Viterbi HMM decode: B=512, T=4096, S=16.  Output = float32 path.
//
// R8: forward exchanges delta half-partials via shared memory (STS + 4x
// LDS.128 broadcast) instead of shuffles; R7 measured SHFL at ~11 cyc each
// (throughput-bound on a lone warp). psi bytes are packed 4 steps per uint32
// (STG amortized to 0.25/step). Arithmetic is bit-identical to the passing
// R7 kernel: c = fl(fl(fmax(v0,v1) + e) + A), exact fmaxf merge, left-
// preference trees, cross-half tie -> half 0 (global first occurrence).
//
// psi format: plane h byte = local_arg(3b) | win_bit(bit 3), win = (v0>=v1).
// Backtrack: b0&8 ? z=b0&7 : z=(b1&7)+8.

#define T_LEN  4096
#define NSTEPS 4095
#define NW4    1024        // packed psi words per plane per batch
#define TILE   256
#define NTILE  16
#define B_TOT  512
#define FULL   0xFFFFFFFFu

__device__ uint32_t      g_psi4[B_TOT][NW4][2][16];         // 64 MB
__device__ unsigned char g_cand[B_TOT][NTILE][TILE][16];    // 32 MB
__device__ unsigned char g_map [B_TOT][NTILE][16];          // 128 KB
__device__ int           g_zT  [B_TOT];

// ---------------- K1: forward pass ----------------
__global__ void __launch_bounds__(128)
hmm_forward_kernel(const float* __restrict__ inputs,
                   const float* __restrict__ hmm)
{
    __shared__ float s_v[4][2][2][16];   // [warp][parity][half][state], 1 KB

    const int warp = threadIdx.x >> 5;
    const int lane = threadIdx.x & 31;
    const int j    = lane & 15;          // state (halves mirror)
    const int h    = lane >> 4;          // which half of predecessors I reduce
    const int i0   = h << 3;             // pred base: 0 or 8
    const int b    = blockIdx.x * 4 + warp;
    const float* xrow  = inputs + b * T_LEN;
    const float* trans = hmm;            // unit 0 only

    // ---- log_A rows for this half; log_pi[j] ----
    float s = 0.0f;
    #pragma unroll
    for (int k = 0; k < 16; k++) s = __fadd_rn(s, trans[j * 16 + k]);
    float ls = logf(s);
    float Ah[8];
    #pragma unroll
    for (int q = 0; q < 8; q++) {
        int i = i0 + q;
        float lt  = logf(trans[i * 16 + j]);
        float lsi = __shfl_sync(FULL, ls, i, 16);
        Ah[q] = __fsub_rn(lt, lsi);
    }
    float log_pi = __fsub_rn(logf(trans[j]), __shfl_sync(FULL, ls, 0, 16));

    const float C_NH = -0.9189385332046727f;  // -0.5*log(2*pi) fp32

    // lazy state: vh = my half's partial max (pre-emission); e_pend pending.
    // true delta[j] = fmax(v0[j], v1[j]) + e_pend (fmax exact).
    float x0 = xrow[0];
    float vh = log_pi;                    // both halves start at log_pi[j]
    float e_pend = __fadd_rn(__fmul_rn(__fmul_rn(-0.5f, x0), x0), C_NH);

    s_v[warp][0][h][j] = vh;              // parity 0 holds step-0 partials
    __syncwarp();

    uint32_t acc = 0;

    auto do_step = [&](float x, int kidx) {
        const int p = kidx & 1;
        // read both halves' partials for my 8 predecessors (broadcast LDS.128)
        float4 a0 = *(const float4*)&s_v[warp][p][0][i0];
        float4 a1 = *(const float4*)&s_v[warp][p][0][i0 + 4];
        float4 b0 = *(const float4*)&s_v[warp][p][1][i0];
        float4 b1 = *(const float4*)&s_v[warp][p][1][i0 + 4];

        float c[8];
        c[0] = __fadd_rn(__fadd_rn(fmaxf(a0.x, b0.x), e_pend), Ah[0]);
        c[1] = __fadd_rn(__fadd_rn(fmaxf(a0.y, b0.y), e_pend), Ah[1]);
        c[2] = __fadd_rn(__fadd_rn(fmaxf(a0.z, b0.z), e_pend), Ah[2]);
        c[3] = __fadd_rn(__fadd_rn(fmaxf(a0.w, b0.w), e_pend), Ah[3]);
        c[4] = __fadd_rn(__fadd_rn(fmaxf(a1.x, b1.x), e_pend), Ah[4]);
        c[5] = __fadd_rn(__fadd_rn(fmaxf(a1.y, b1.y), e_pend), Ah[5]);
        c[6] = __fadd_rn(__fadd_rn(fmaxf(a1.z, b1.z), e_pend), Ah[6]);
        c[7] = __fadd_rn(__fadd_rn(fmaxf(a1.w, b1.w), e_pend), Ah[7]);

        float e_new = __fadd_rn(__fmul_rn(__fmul_rn(-0.5f, x), x), C_NH);

        // 8-way max (FMNMX chain on the critical path) + first-occ argmax
        float v4[4]; int id4[4];
        #pragma unroll
        for (int q = 0; q < 4; q++) {
            bool pq = c[2*q] >= c[2*q+1];
            v4[q]  = fmaxf(c[2*q], c[2*q+1]);
            id4[q] = pq ? (2*q) : (2*q + 1);
        }
        float v2[2]; int id2[2];
        #pragma unroll
        for (int q = 0; q < 2; q++) {
            bool pq = v4[2*q] >= v4[2*q+1];
            v2[q]  = fmaxf(v4[2*q], v4[2*q+1]);
            id2[q] = pq ? id4[2*q] : id4[2*q+1];
        }
        bool pl = v2[0] >= v2[1];
        float vn = fmaxf(v2[0], v2[1]);
        int argh = pl ? id2[0] : id2[1];       // local 0..7

        // publish next partials ASAP, then sync (the one sync per step)
        s_v[warp][p ^ 1][h][j] = vn;
        __syncwarp();

        // psi (off the delta chain): win = (v0 >= v1) globally
        float vo = __shfl_xor_sync(FULL, vn, 16);
        bool win = h ? (vo >= vn) : (vn >= vo);
        uint32_t byte = (uint32_t)argh | (win ? 8u : 0u);
        acc |= byte << ((kidx & 3) * 8);
        if ((kidx & 3) == 3) { g_psi4[b][kidx >> 2][h][j] = acc; acc = 0; }

        vh = vn;
        e_pend = e_new;
    };

    // forward: 511 blocks of 8 steps + 7 tail, input prefetched 8 ahead
    float xs[8];
    #pragma unroll
    for (int k = 0; k < 8; k++) xs[k] = __ldg(xrow + 1 + k);
    int t = 1;
    for (int blk = 0; blk < 511; blk++) {
        float xn[8];
        #pragma unroll
        for (int k = 0; k < 8; k++) {
            int nt = t + 8 + k;
            nt = nt < T_LEN ? nt : T_LEN - 1;
            xn[k] = __ldg(xrow + nt);
        }
        #pragma unroll
        for (int k = 0; k < 8; k++) do_step(xs[k], t - 1 + k);
        #pragma unroll
        for (int k = 0; k < 8; k++) xs[k] = xn[k];
        t += 8;
    }
    #pragma unroll
    for (int k = 0; k < 7; k++) do_step(xs[k], t - 1 + k);   // kidx 4088..4094

    // flush partial psi word (kidx 4092..4094 -> word 1023, bytes 0..2)
    g_psi4[b][NW4 - 1][h][j] = acc;
    __syncwarp();

    // materialize final delta, zT = argmax (first occurrence)
    float vo = __shfl_xor_sync(FULL, vh, 16);
    float delta = __fadd_rn(fmaxf(vh, vo), e_pend);
    float v = delta; int zi = j;
    #pragma unroll
    for (int o = 8; o > 0; o >>= 1) {
        float v2 = __shfl_xor_sync(FULL, v, o, 16);
        int   i2 = __shfl_xor_sync(FULL, zi, o, 16);
        if (v2 > v || (v2 == v && i2 < zi)) { v = v2; zi = i2; }
    }
    if (lane == 0) g_zT[b] = zi;
}

// ---------------- K2: per-tile candidate chase ----------------
__global__ void __launch_bounds__(128)
hmm_chase_kernel()
{
    __shared__ uint32_t s_w[4][TILE / 4][2][16];   // 32 KB

    const int warp = threadIdx.x >> 5;
    const int lane = threadIdx.x & 31;
    const int b    = blockIdx.x;
    const int tile = blockIdx.y * 4 + warp;

    // stage this tile's packed psi (8 KB) into smem, coalesced
    const uint4* src = reinterpret_cast<const uint4*>(&g_psi4[b][tile * (TILE / 4)][0][0]);
    uint4* dst = reinterpret_cast<uint4*>(&s_w[warp][0][0][0]);
    #pragma unroll
    for (int i = 0; i < 16; i++) dst[lane + 32 * i] = src[lane + 32 * i];
    __syncwarp();

    // chase all 16 candidate end states (lanes 16-31 mirror, stores masked)
    int z = lane & 15;
    const int kmax = (tile == NTILE - 1) ? (TILE - 2) : (TILE - 1);
    const bool st = (lane < 16);
    for (int k = kmax; k >= 0; k--) {
        int sh = (k & 3) * 8;
        uint32_t w0 = s_w[warp][k >> 2][0][z];
        uint32_t w1 = s_w[warp][k >> 2][1][z];
        uint32_t p0 = (w0 >> sh) & 0xFFu;
        z = (p0 & 8u) ? (int)(p0 & 7u) : (int)(((w1 >> sh) & 7u) | 8u);
        if (st) g_cand[b][tile][k][lane] = (unsigned char)z;
    }
    if (st) g_map[b][tile][lane] = (unsigned char)z;
}

// ---------------- K3: compose maps + emit path ----------------
__global__ void __launch_bounds__(128)
hmm_emit_kernel(float* __restrict__ out)
{
    __shared__ unsigned char e_tile[NTILE];
    const int b = blockIdx.x;

    if (threadIdx.x == 0) {
        int z = g_zT[b];
        e_tile[NTILE - 1] = (unsigned char)z;
        #pragma unroll
        for (int tau = NTILE - 1; tau >= 1; tau--) {
            z = g_map[b][tau][z];
            e_tile[tau - 1] = (unsigned char)z;
        }
    }
    __syncthreads();

    float* orow = out + b * T_LEN;
    for (int t = threadIdx.x; t < NSTEPS; t += 128) {
        int tau = t >> 8, k = t & (TILE - 1);
        orow[t] = (float)g_cand[b][tau][k][e_tile[tau]];
    }
    if (threadIdx.x == 0) orow[T_LEN - 1] = (float)g_zT[b];
}

extern "C" void kernel_launch(void* const* d_in, const int* in_sizes, int n_in,
                              void* d_out, int out_size)
{
    const float* inputs;
    const float* hmm;
    if (in_sizes[0] < in_sizes[1]) {
        hmm    = (const float*)d_in[0];
        inputs = (const float*)d_in[1];
    } else {
        inputs = (const float*)d_in[0];
        hmm    = (const float*)d_in[1];
    }
    hmm_forward_kernel<<<128, 128>>>(inputs, hmm);
    hmm_chase_kernel<<<dim3(B_TOT, 4), 128>>>();
    hmm_emit_kernel<<<B_TOT, 128>>>((float*)d_out);
}